// round 1
// baseline (speedup 1.0000x reference)
#include <cuda_runtime.h>
#include <cstdint>

// ---------------------------------------------------------------------------
// BaseGCN: 4x GCNConv (8->16->32->64->128) + PReLU, mean-pool over 64 graphs,
// linear 128->4.  N=100000 nodes, E=1600000 edges.
// ---------------------------------------------------------------------------

#define NMAX 100352      // >= N, padded
#define EMAX 1600000

// Scratch (device globals; no runtime allocation)
__device__ float g_dinv[NMAX];
__device__ float g_norm[EMAX];
__device__ float g_tmp[(size_t)NMAX * 128];
__device__ float g_ha [(size_t)NMAX * 128];
__device__ float g_hb [(size_t)NMAX * 128];

static inline int cdiv(long a, long b) { return (int)((a + b - 1) / b); }

// ---------------- degree / norm precompute ----------------
__global__ void k_deg_init(float* __restrict__ deg, int n) {
    int i = blockIdx.x * blockDim.x + threadIdx.x;
    if (i < n) deg[i] = 1.0f;                  // self-loop contributes 1
}

__global__ void k_deg_edge(const int* __restrict__ dst, float* __restrict__ deg, int e) {
    int i = blockIdx.x * blockDim.x + threadIdx.x;
    if (i < e) atomicAdd(&deg[dst[i]], 1.0f);
}

__global__ void k_dinv(float* __restrict__ deg, int n) {
    int i = blockIdx.x * blockDim.x + threadIdx.x;
    if (i < n) deg[i] = rsqrtf(deg[i]);        // deg >= 1 always
}

__global__ void k_norm(const int* __restrict__ src, const int* __restrict__ dst,
                       const float* __restrict__ dinv, float* __restrict__ norm, int e) {
    int i = blockIdx.x * blockDim.x + threadIdx.x;
    if (i < e) norm[i] = __ldg(&dinv[src[i]]) * __ldg(&dinv[dst[i]]);
}

// ---------------- fused GEMM + PReLU(input) + self-loop init ----------------
// tmp[row] = prelu(in[row]) @ W
// out[row] = b + tmp[row] * dinv[row]^2        (self-loop message)
template<int FIN, int FOUT, bool PRELU>
__global__ void k_gemm(const float* __restrict__ in, const float* __restrict__ W,
                       const float* __restrict__ bias, const float* __restrict__ aP,
                       const float* __restrict__ dinv,
                       float* __restrict__ tmp, float* __restrict__ out, int n) {
    __shared__ float Ws[FIN * FOUT];
    __shared__ float bs[FOUT];
    for (int i = threadIdx.x; i < FIN * FOUT; i += blockDim.x) Ws[i] = W[i];
    if (threadIdx.x < FOUT) bs[threadIdx.x] = bias[threadIdx.x];
    float a = 0.0f;
    if (PRELU) a = __ldg(aP);
    __syncthreads();

    int row = blockIdx.x * blockDim.x + threadIdx.x;
    if (row >= n) return;

    float r[FIN];
    const float4* inr = reinterpret_cast<const float4*>(in + (size_t)row * FIN);
#pragma unroll
    for (int k4 = 0; k4 < FIN / 4; k4++) {
        float4 v = __ldg(inr + k4);
        if (PRELU) {
            v.x = v.x >= 0.f ? v.x : a * v.x;
            v.y = v.y >= 0.f ? v.y : a * v.y;
            v.z = v.z >= 0.f ? v.z : a * v.z;
            v.w = v.w >= 0.f ? v.w : a * v.w;
        }
        r[4 * k4 + 0] = v.x; r[4 * k4 + 1] = v.y;
        r[4 * k4 + 2] = v.z; r[4 * k4 + 3] = v.w;
    }
    float d = __ldg(&dinv[row]);
    float dd = d * d;
    float* trow = tmp + (size_t)row * FOUT;
    float* orow = out + (size_t)row * FOUT;

#pragma unroll 2
    for (int c = 0; c < FOUT; c += 4) {
        float4 acc = {0.f, 0.f, 0.f, 0.f};
#pragma unroll
        for (int k = 0; k < FIN; k++) {
            float4 w = *reinterpret_cast<const float4*>(&Ws[k * FOUT + c]);
            acc.x += r[k] * w.x; acc.y += r[k] * w.y;
            acc.z += r[k] * w.z; acc.w += r[k] * w.w;
        }
        *reinterpret_cast<float4*>(trow + c) = acc;
        float4 o;
        o.x = bs[c + 0] + acc.x * dd;
        o.y = bs[c + 1] + acc.y * dd;
        o.z = bs[c + 2] + acc.z * dd;
        o.w = bs[c + 3] + acc.w * dd;
        *reinterpret_cast<float4*>(orow + c) = o;
    }
}

// ---------------- edge scatter: out[dst] += tmp[src] * norm ----------------
// F/4 threads cooperate per edge; 16B vector gathers + 16B vector reductions.
template<int F>
__global__ void k_edge(const int* __restrict__ src, const int* __restrict__ dst,
                       const float* __restrict__ norm, const float* __restrict__ tmp,
                       float* __restrict__ out, int e) {
    constexpr int TPE = F / 4;
    long gid = (long)blockIdx.x * blockDim.x + threadIdx.x;
    int eidx = (int)(gid / TPE);
    int lane = (int)(gid % TPE);
    if (eidx >= e) return;
    int s = __ldg(&src[eidx]);
    int d = __ldg(&dst[eidx]);
    float nm = __ldg(&norm[eidx]);
    float4 v = __ldg(reinterpret_cast<const float4*>(tmp + (size_t)s * F) + lane);
    v.x *= nm; v.y *= nm; v.z *= nm; v.w *= nm;
    float* p = out + (size_t)d * F + lane * 4;
    asm volatile("red.global.add.v4.f32 [%0], {%1, %2, %3, %4};"
                 :: "l"(p), "f"(v.x), "f"(v.y), "f"(v.z), "f"(v.w) : "memory");
}

// ---------------- pool (mean per graph) + final linear ----------------
__device__ __forceinline__ int lower_bound_i(const int* b, int n, int v) {
    int lo = 0, hi = n;
    while (lo < hi) {
        int m = (lo + hi) >> 1;
        if (__ldg(&b[m]) < v) lo = m + 1; else hi = m;
    }
    return lo;
}

__global__ void k_pool(const float* __restrict__ h, const int* __restrict__ batch,
                       const float* __restrict__ Wlin, const float* __restrict__ blin,
                       float* __restrict__ out, int n) {
    const int F = 128;
    int g = blockIdx.x;
    int start = lower_bound_i(batch, n, g);
    int end   = lower_bound_i(batch, n, g + 1);

    int c    = threadIdx.x & (F - 1);
    int half = threadIdx.x >> 7;
    float acc = 0.f;
    for (int r = start + half; r < end; r += 2)
        acc += __ldg(&h[(size_t)r * F + c]);

    __shared__ float sm[256];
    __shared__ float pooled[F];
    sm[threadIdx.x] = acc;
    __syncthreads();
    if (threadIdx.x < F) {
        int cnt = end - start;
        float denom = (float)(cnt > 1 ? cnt : 1);
        pooled[threadIdx.x] = (sm[threadIdx.x] + sm[threadIdx.x + F]) / denom;
    }
    __syncthreads();
    if (threadIdx.x < 4) {
        float s = __ldg(&blin[threadIdx.x]);
#pragma unroll 8
        for (int f = 0; f < F; f++)
            s += pooled[f] * __ldg(&Wlin[f * 4 + threadIdx.x]);
        out[g * 4 + threadIdx.x] = s;
    }
}

// ---------------------------------------------------------------------------
extern "C" void kernel_launch(void* const* d_in, const int* in_sizes, int n_in,
                              void* d_out, int out_size) {
    const float* x    = (const float*)d_in[0];
    const int* esrc   = (const int*)d_in[1];
    const int* edst   = (const int*)d_in[2];
    const int* batch  = (const int*)d_in[3];
    const float* W1   = (const float*)d_in[4];
    const float* b1   = (const float*)d_in[5];
    const float* W2   = (const float*)d_in[6];
    const float* b2   = (const float*)d_in[7];
    const float* W3   = (const float*)d_in[8];
    const float* b3   = (const float*)d_in[9];
    const float* W4   = (const float*)d_in[10];
    const float* b4   = (const float*)d_in[11];
    const float* a1   = (const float*)d_in[12];
    const float* a2   = (const float*)d_in[13];
    const float* a3   = (const float*)d_in[14];
    const float* Wlin = (const float*)d_in[15];
    const float* blin = (const float*)d_in[16];
    float* out = (float*)d_out;

    int n = in_sizes[0] / 8;   // x is [N, 8]
    int e = in_sizes[1];
    int G = out_size / 4;

    float *dinv, *nrm, *tmp, *ha, *hb;
    cudaGetSymbolAddress((void**)&dinv, g_dinv);
    cudaGetSymbolAddress((void**)&nrm,  g_norm);
    cudaGetSymbolAddress((void**)&tmp,  g_tmp);
    cudaGetSymbolAddress((void**)&ha,   g_ha);
    cudaGetSymbolAddress((void**)&hb,   g_hb);

    const int T = 256;
    // degree + norm
    k_deg_init<<<cdiv(n, T), T>>>(dinv, n);
    k_deg_edge<<<cdiv(e, T), T>>>(edst, dinv, e);
    k_dinv<<<cdiv(n, T), T>>>(dinv, n);
    k_norm<<<cdiv(e, T), T>>>(esrc, edst, dinv, nrm, e);

    // Layer 1: x[N,8] -> hb[N,16]
    k_gemm<8, 16, false><<<cdiv(n, T), T>>>(x, W1, b1, nullptr, dinv, tmp, hb, n);
    k_edge<16><<<cdiv((long)e * 4, T), T>>>(esrc, edst, nrm, tmp, hb, e);

    // Layer 2: prelu(hb,a1)[N,16] -> ha[N,32]
    k_gemm<16, 32, true><<<cdiv(n, T), T>>>(hb, W2, b2, a1, dinv, tmp, ha, n);
    k_edge<32><<<cdiv((long)e * 8, T), T>>>(esrc, edst, nrm, tmp, ha, e);

    // Layer 3: prelu(ha,a2)[N,32] -> hb[N,64]
    k_gemm<32, 64, true><<<cdiv(n, T), T>>>(ha, W3, b3, a2, dinv, tmp, hb, n);
    k_edge<64><<<cdiv((long)e * 16, T), T>>>(esrc, edst, nrm, tmp, hb, e);

    // Layer 4: prelu(hb,a3)[N,64] -> ha[N,128]
    k_gemm<64, 128, true><<<cdiv(n, T), T>>>(hb, W4, b4, a3, dinv, tmp, ha, n);
    k_edge<128><<<cdiv((long)e * 32, T), T>>>(esrc, edst, nrm, tmp, ha, e);

    // Pool + linear head
    k_pool<<<G, 256>>>(ha, batch, Wlin, blin, out, n);
}

// round 2
// speedup vs baseline: 1.3995x; 1.3995x over previous
#include <cuda_runtime.h>
#include <cstdint>

// ---------------------------------------------------------------------------
// BaseGCN: 4x GCNConv (8->16->32->64->128) + PReLU, mean-pool over 64 graphs,
// linear 128->4.  N=100000 nodes, E=1600000 edges.
// Round 2: pull-mode CSR aggregation (no float atomics, 1 write per node row).
// ---------------------------------------------------------------------------

#define NMAX 100352      // >= N, padded
#define EMAX 1600000
#define SCAN_BLK 1024

// Scratch (device globals; no runtime allocation)
__device__ float g_dinv[NMAX];
__device__ int   g_deg [NMAX];
__device__ int   g_fill[NMAX];
__device__ int   g_rowptr[NMAX + 1];
__device__ int   g_bsums[256];
__device__ int   g_col  [EMAX];
__device__ float g_cnorm[EMAX];
__device__ float g_tmp[(size_t)NMAX * 128];
__device__ float g_ha [(size_t)NMAX * 128];
__device__ float g_hb [(size_t)NMAX * 128];

static inline int cdiv(long a, long b) { return (int)((a + b - 1) / b); }

// ---------------- degree / CSR build ----------------
__global__ void k_zero(int* __restrict__ deg, int* __restrict__ fill, int n) {
    int i = blockIdx.x * blockDim.x + threadIdx.x;
    if (i < n) { deg[i] = 0; fill[i] = 0; }
}

__global__ void k_count(const int* __restrict__ dst, int* __restrict__ deg, int e) {
    int i = blockIdx.x * blockDim.x + threadIdx.x;
    if (i < e) atomicAdd(&deg[dst[i]], 1);
}

__global__ void k_dinv(const int* __restrict__ deg, float* __restrict__ dinv, int n) {
    int i = blockIdx.x * blockDim.x + threadIdx.x;
    if (i < n) dinv[i] = rsqrtf((float)deg[i] + 1.0f);   // +1 self-loop
}

// Block-level exclusive scan (Hillis-Steele), block totals to bsums
__global__ void k_scan1(const int* __restrict__ deg, int* __restrict__ rowptr,
                        int* __restrict__ bsums, int n) {
    __shared__ int sm[SCAN_BLK];
    int i = blockIdx.x * SCAN_BLK + threadIdx.x;
    int v = (i < n) ? deg[i] : 0;
    sm[threadIdx.x] = v;
    __syncthreads();
#pragma unroll
    for (int off = 1; off < SCAN_BLK; off <<= 1) {
        int t = (threadIdx.x >= off) ? sm[threadIdx.x - off] : 0;
        __syncthreads();
        sm[threadIdx.x] += t;
        __syncthreads();
    }
    if (i < n) rowptr[i] = sm[threadIdx.x] - v;           // exclusive
    if (threadIdx.x == SCAN_BLK - 1) bsums[blockIdx.x] = sm[SCAN_BLK - 1];
}

__global__ void k_scan2(int* __restrict__ bsums, int nb) {
    __shared__ int sm[256];
    int v = (threadIdx.x < nb) ? bsums[threadIdx.x] : 0;
    sm[threadIdx.x] = v;
    __syncthreads();
#pragma unroll
    for (int off = 1; off < 256; off <<= 1) {
        int t = (threadIdx.x >= off) ? sm[threadIdx.x - off] : 0;
        __syncthreads();
        sm[threadIdx.x] += t;
        __syncthreads();
    }
    if (threadIdx.x < nb) bsums[threadIdx.x] = sm[threadIdx.x] - v;  // exclusive
}

__global__ void k_scan3(int* __restrict__ rowptr, const int* __restrict__ bsums,
                        int n, int e) {
    int i = blockIdx.x * blockDim.x + threadIdx.x;
    if (i < n) rowptr[i] += bsums[i / SCAN_BLK];
    if (i == 0) rowptr[n] = e;
}

__global__ void k_fillcsr(const int* __restrict__ src, const int* __restrict__ dst,
                          const float* __restrict__ dinv, const int* __restrict__ rowptr,
                          int* __restrict__ fill, int* __restrict__ col,
                          float* __restrict__ cnorm, int e) {
    int i = blockIdx.x * blockDim.x + threadIdx.x;
    if (i >= e) return;
    int d = dst[i], s = src[i];
    int pos = __ldg(&rowptr[d]) + atomicAdd(&fill[d], 1);
    col[pos] = s;
    cnorm[pos] = __ldg(&dinv[s]) * __ldg(&dinv[d]);
}

// ---------------- fused GEMM + PReLU(input):  tmp = prelu(in) @ W ----------
template<int FIN, int FOUT, bool PRELU>
__global__ void k_gemm(const float* __restrict__ in, const float* __restrict__ W,
                       const float* __restrict__ aP,
                       float* __restrict__ tmp, int n) {
    __shared__ float Ws[FIN * FOUT];
    for (int i = threadIdx.x; i < FIN * FOUT; i += blockDim.x) Ws[i] = W[i];
    float a = 0.0f;
    if (PRELU) a = __ldg(aP);
    __syncthreads();

    int row = blockIdx.x * blockDim.x + threadIdx.x;
    if (row >= n) return;

    float r[FIN];
    const float4* inr = reinterpret_cast<const float4*>(in + (size_t)row * FIN);
#pragma unroll
    for (int k4 = 0; k4 < FIN / 4; k4++) {
        float4 v = __ldg(inr + k4);
        if (PRELU) {
            v.x = v.x >= 0.f ? v.x : a * v.x;
            v.y = v.y >= 0.f ? v.y : a * v.y;
            v.z = v.z >= 0.f ? v.z : a * v.z;
            v.w = v.w >= 0.f ? v.w : a * v.w;
        }
        r[4 * k4 + 0] = v.x; r[4 * k4 + 1] = v.y;
        r[4 * k4 + 2] = v.z; r[4 * k4 + 3] = v.w;
    }
    float* trow = tmp + (size_t)row * FOUT;
#pragma unroll 2
    for (int c = 0; c < FOUT; c += 4) {
        float4 acc = {0.f, 0.f, 0.f, 0.f};
#pragma unroll
        for (int k = 0; k < FIN; k++) {
            float4 w = *reinterpret_cast<const float4*>(&Ws[k * FOUT + c]);
            acc.x += r[k] * w.x; acc.y += r[k] * w.y;
            acc.z += r[k] * w.z; acc.w += r[k] * w.w;
        }
        *reinterpret_cast<float4*>(trow + c) = acc;
    }
}

// ---------------- pull aggregation: out[v] = b + dinv[v]^2*tmp[v]
//                                  + sum_{e in CSR[v]} tmp[col[e]] * cnorm[e]
template<int F>
__global__ void k_agg(const int* __restrict__ rowptr, const int* __restrict__ col,
                      const float* __restrict__ cnorm, const float* __restrict__ tmp,
                      const float* __restrict__ bias, const float* __restrict__ dinv,
                      float* __restrict__ out, int n) {
    constexpr int TPE = F / 4;
    long gid = (long)blockIdx.x * blockDim.x + threadIdx.x;
    int node = (int)(gid / TPE);
    int lane = (int)(gid % TPE);
    if (node >= n) return;

    int beg = __ldg(&rowptr[node]);
    int end = __ldg(&rowptr[node + 1]);
    float d = __ldg(&dinv[node]);
    float dd = d * d;

    const float4* t4 = reinterpret_cast<const float4*>(tmp);
    float4 self = __ldg(t4 + (size_t)node * TPE + lane);
    float4 bv   = __ldg(reinterpret_cast<const float4*>(bias) + lane);
    float4 acc;
    acc.x = bv.x + self.x * dd;
    acc.y = bv.y + self.y * dd;
    acc.z = bv.z + self.z * dd;
    acc.w = bv.w + self.w * dd;

    for (int p = beg; p < end; p++) {
        int s = __ldg(&col[p]);
        float nm = __ldg(&cnorm[p]);
        float4 v = __ldg(t4 + (size_t)s * TPE + lane);
        acc.x += v.x * nm; acc.y += v.y * nm;
        acc.z += v.z * nm; acc.w += v.w * nm;
    }
    reinterpret_cast<float4*>(out)[(size_t)node * TPE + lane] = acc;
}

// ---------------- pool (mean per graph) + final linear ----------------
__device__ __forceinline__ int lower_bound_i(const int* b, int n, int v) {
    int lo = 0, hi = n;
    while (lo < hi) {
        int m = (lo + hi) >> 1;
        if (__ldg(&b[m]) < v) lo = m + 1; else hi = m;
    }
    return lo;
}

__global__ void k_pool(const float* __restrict__ h, const int* __restrict__ batch,
                       const float* __restrict__ Wlin, const float* __restrict__ blin,
                       float* __restrict__ out, int n) {
    const int F = 128;
    int g = blockIdx.x;
    int start = lower_bound_i(batch, n, g);
    int end   = lower_bound_i(batch, n, g + 1);

    int c    = threadIdx.x & (F - 1);
    int half = threadIdx.x >> 7;
    float acc = 0.f;
    for (int r = start + half; r < end; r += 2)
        acc += __ldg(&h[(size_t)r * F + c]);

    __shared__ float sm[256];
    __shared__ float pooled[F];
    sm[threadIdx.x] = acc;
    __syncthreads();
    if (threadIdx.x < F) {
        int cnt = end - start;
        float denom = (float)(cnt > 1 ? cnt : 1);
        pooled[threadIdx.x] = (sm[threadIdx.x] + sm[threadIdx.x + F]) / denom;
    }
    __syncthreads();
    if (threadIdx.x < 4) {
        float s = __ldg(&blin[threadIdx.x]);
#pragma unroll 8
        for (int f = 0; f < F; f++)
            s += pooled[f] * __ldg(&Wlin[f * 4 + threadIdx.x]);
        out[g * 4 + threadIdx.x] = s;
    }
}

// ---------------------------------------------------------------------------
extern "C" void kernel_launch(void* const* d_in, const int* in_sizes, int n_in,
                              void* d_out, int out_size) {
    const float* x    = (const float*)d_in[0];
    const int* esrc   = (const int*)d_in[1];
    const int* edst   = (const int*)d_in[2];
    const int* batch  = (const int*)d_in[3];
    const float* W1   = (const float*)d_in[4];
    const float* b1   = (const float*)d_in[5];
    const float* W2   = (const float*)d_in[6];
    const float* b2   = (const float*)d_in[7];
    const float* W3   = (const float*)d_in[8];
    const float* b3   = (const float*)d_in[9];
    const float* W4   = (const float*)d_in[10];
    const float* b4   = (const float*)d_in[11];
    const float* a1   = (const float*)d_in[12];
    const float* a2   = (const float*)d_in[13];
    const float* a3   = (const float*)d_in[14];
    const float* Wlin = (const float*)d_in[15];
    const float* blin = (const float*)d_in[16];
    float* out = (float*)d_out;

    int n = in_sizes[0] / 8;   // x is [N, 8]
    int e = in_sizes[1];
    int G = out_size / 4;

    float *dinv, *cnorm, *tmp, *ha, *hb;
    int *deg, *fill, *rowptr, *bsums, *col;
    cudaGetSymbolAddress((void**)&dinv,   g_dinv);
    cudaGetSymbolAddress((void**)&deg,    g_deg);
    cudaGetSymbolAddress((void**)&fill,   g_fill);
    cudaGetSymbolAddress((void**)&rowptr, g_rowptr);
    cudaGetSymbolAddress((void**)&bsums,  g_bsums);
    cudaGetSymbolAddress((void**)&col,    g_col);
    cudaGetSymbolAddress((void**)&cnorm,  g_cnorm);
    cudaGetSymbolAddress((void**)&tmp,    g_tmp);
    cudaGetSymbolAddress((void**)&ha,     g_ha);
    cudaGetSymbolAddress((void**)&hb,     g_hb);

    const int T = 256;
    int nscan = cdiv(n, SCAN_BLK);

    // degree, dinv, CSR build
    k_zero <<<cdiv(n, T), T>>>(deg, fill, n);
    k_count<<<cdiv(e, T), T>>>(edst, deg, e);
    k_dinv <<<cdiv(n, T), T>>>(deg, dinv, n);
    k_scan1<<<nscan, SCAN_BLK>>>(deg, rowptr, bsums, n);
    k_scan2<<<1, 256>>>(bsums, nscan);
    k_scan3<<<cdiv(n, T), T>>>(rowptr, bsums, n, e);
    k_fillcsr<<<cdiv(e, T), T>>>(esrc, edst, dinv, rowptr, fill, col, cnorm, e);

    // Layer 1: x[N,8] -> hb[N,16]
    k_gemm<8, 16, false><<<cdiv(n, T), T>>>(x, W1, nullptr, tmp, n);
    k_agg<16><<<cdiv((long)n * 4, T), T>>>(rowptr, col, cnorm, tmp, b1, dinv, hb, n);

    // Layer 2: prelu(hb,a1)[N,16] -> ha[N,32]
    k_gemm<16, 32, true><<<cdiv(n, T), T>>>(hb, W2, a1, tmp, n);
    k_agg<32><<<cdiv((long)n * 8, T), T>>>(rowptr, col, cnorm, tmp, b2, dinv, ha, n);

    // Layer 3: prelu(ha,a2)[N,32] -> hb[N,64]
    k_gemm<32, 64, true><<<cdiv(n, T), T>>>(ha, W3, a2, tmp, n);
    k_agg<64><<<cdiv((long)n * 16, T), T>>>(rowptr, col, cnorm, tmp, b3, dinv, hb, n);

    // Layer 4: prelu(hb,a3)[N,64] -> ha[N,128]
    k_gemm<64, 128, true><<<cdiv(n, T), T>>>(hb, W4, a3, tmp, n);
    k_agg<128><<<cdiv((long)n * 32, T), T>>>(rowptr, col, cnorm, tmp, b4, dinv, ha, n);

    // Pool + linear head
    k_pool<<<G, 256>>>(ha, batch, Wlin, blin, out, n);
}

// round 3
// speedup vs baseline: 2.3687x; 1.6925x over previous
#include <cuda_runtime.h>
#include <cstdint>

// ---------------------------------------------------------------------------
// BaseGCN: 4x GCNConv (8->16->32->64->128) + PReLU, mean-pool, linear head.
// Round 3: aggregate in INPUT space (halves gather bytes), and commute the
// mean-pool past the (linear) layer-4 GEMM + head: pool z4 (64-wide), then
// apply the precomposed 64x4 matrix W4@Wlin once per graph.
// ---------------------------------------------------------------------------

#define NMAX 100352
#define EMAX 1600000
#define SCAN_BLK 1024

__device__ float g_dinv[NMAX];
__device__ int   g_deg [NMAX];
__device__ int   g_fill[NMAX];
__device__ int   g_rowptr[NMAX + 1];
__device__ int   g_bsums[256];
__device__ int   g_col  [EMAX];
__device__ float g_cnorm[EMAX];
__device__ float g_z [(size_t)NMAX * 64];   // aggregated (input-space) buffer
__device__ float g_ha[(size_t)NMAX * 64];   // activations
__device__ float g_hb[(size_t)NMAX * 64];
__device__ float g_Wc[64 * 4];              // W4 @ Wlin
__device__ float g_bc[4];                   // b4 @ Wlin + blin

static inline int cdiv(long a, long b) { return (int)((a + b - 1) / b); }

// ---------------- degree / CSR build ----------------
__global__ void k_zero(int* __restrict__ deg, int* __restrict__ fill, int n) {
    int i = blockIdx.x * blockDim.x + threadIdx.x;
    if (i < n) { deg[i] = 0; fill[i] = 0; }
}

__global__ void k_count(const int* __restrict__ dst, int* __restrict__ deg, int e) {
    int i = blockIdx.x * blockDim.x + threadIdx.x;
    if (i < e) atomicAdd(&deg[dst[i]], 1);
}

__global__ void k_dinv(const int* __restrict__ deg, float* __restrict__ dinv, int n) {
    int i = blockIdx.x * blockDim.x + threadIdx.x;
    if (i < n) dinv[i] = rsqrtf((float)deg[i] + 1.0f);   // +1 self-loop
}

__global__ void k_scan1(const int* __restrict__ deg, int* __restrict__ rowptr,
                        int* __restrict__ bsums, int n) {
    __shared__ int sm[SCAN_BLK];
    int i = blockIdx.x * SCAN_BLK + threadIdx.x;
    int v = (i < n) ? deg[i] : 0;
    sm[threadIdx.x] = v;
    __syncthreads();
#pragma unroll
    for (int off = 1; off < SCAN_BLK; off <<= 1) {
        int t = (threadIdx.x >= off) ? sm[threadIdx.x - off] : 0;
        __syncthreads();
        sm[threadIdx.x] += t;
        __syncthreads();
    }
    if (i < n) rowptr[i] = sm[threadIdx.x] - v;           // exclusive
    if (threadIdx.x == SCAN_BLK - 1) bsums[blockIdx.x] = sm[SCAN_BLK - 1];
}

__global__ void k_scan2(int* __restrict__ bsums, int nb) {
    __shared__ int sm[256];
    int v = (threadIdx.x < nb) ? bsums[threadIdx.x] : 0;
    sm[threadIdx.x] = v;
    __syncthreads();
#pragma unroll
    for (int off = 1; off < 256; off <<= 1) {
        int t = (threadIdx.x >= off) ? sm[threadIdx.x - off] : 0;
        __syncthreads();
        sm[threadIdx.x] += t;
        __syncthreads();
    }
    if (threadIdx.x < nb) bsums[threadIdx.x] = sm[threadIdx.x] - v;  // exclusive
}

__global__ void k_scan3(int* __restrict__ rowptr, const int* __restrict__ bsums,
                        int n, int e) {
    int i = blockIdx.x * blockDim.x + threadIdx.x;
    if (i < n) rowptr[i] += bsums[i / SCAN_BLK];
    if (i == 0) rowptr[n] = e;
}

__global__ void k_fillcsr(const int* __restrict__ src, const int* __restrict__ dst,
                          const float* __restrict__ dinv, const int* __restrict__ rowptr,
                          int* __restrict__ fill, int* __restrict__ col,
                          float* __restrict__ cnorm, int e) {
    int i = blockIdx.x * blockDim.x + threadIdx.x;
    if (i >= e) return;
    int d = dst[i], s = src[i];
    int pos = __ldg(&rowptr[d]) + atomicAdd(&fill[d], 1);
    col[pos] = s;
    cnorm[pos] = __ldg(&dinv[s]) * __ldg(&dinv[d]);
}

// ---------------- head precompose: Wc = W4 @ Wlin, bc = b4 @ Wlin + blin ----
__global__ void k_head(const float* __restrict__ W4, const float* __restrict__ b4,
                       const float* __restrict__ Wlin, const float* __restrict__ blin,
                       float* __restrict__ Wc, float* __restrict__ bc) {
    int t = threadIdx.x;                  // 256 threads: i = t/4 in [0,64), c = t%4
    int i = t >> 2, c = t & 3;
    float s = 0.f;
#pragma unroll 8
    for (int k = 0; k < 128; k++)
        s += __ldg(&W4[i * 128 + k]) * __ldg(&Wlin[k * 4 + c]);
    Wc[i * 4 + c] = s;
    if (i == 0) {
        float b = __ldg(&blin[c]);
#pragma unroll 8
        for (int k = 0; k < 128; k++)
            b += __ldg(&b4[k]) * __ldg(&Wlin[k * 4 + c]);
        bc[c] = b;
    }
}

// ---------------- pull aggregation (input space, no bias) -------------------
// z[v] = dinv[v]^2 * h[v] + sum_{e in CSR[v]} h[col[e]] * cnorm[e]
template<int F>
__global__ void k_agg(const int* __restrict__ rowptr, const int* __restrict__ col,
                      const float* __restrict__ cnorm, const float* __restrict__ h,
                      const float* __restrict__ dinv,
                      float* __restrict__ z, int n) {
    constexpr int TPE = F / 4;
    long gid = (long)blockIdx.x * blockDim.x + threadIdx.x;
    int node = (int)(gid / TPE);
    int lane = (int)(gid % TPE);
    if (node >= n) return;

    int beg = __ldg(&rowptr[node]);
    int end = __ldg(&rowptr[node + 1]);
    float d = __ldg(&dinv[node]);
    float dd = d * d;

    const float4* h4 = reinterpret_cast<const float4*>(h);
    float4 self = __ldg(h4 + (size_t)node * TPE + lane);
    float4 acc;
    acc.x = self.x * dd; acc.y = self.y * dd;
    acc.z = self.z * dd; acc.w = self.w * dd;

    for (int p = beg; p < end; p++) {
        int s = __ldg(&col[p]);
        float nm = __ldg(&cnorm[p]);
        float4 v = __ldg(h4 + (size_t)s * TPE + lane);
        acc.x += v.x * nm; acc.y += v.y * nm;
        acc.z += v.z * nm; acc.w += v.w * nm;
    }
    reinterpret_cast<float4*>(z)[(size_t)node * TPE + lane] = acc;
}

// ---------------- GEMM (+bias, +optional PReLU on output) -------------------
// h_out[row] = prelu(z[row] @ W + b)
template<int FIN, int FOUT, bool PRELU>
__global__ void k_gemm(const float* __restrict__ z, const float* __restrict__ W,
                       const float* __restrict__ bias, const float* __restrict__ aP,
                       float* __restrict__ out, int n) {
    __shared__ float Ws[FIN * FOUT];
    __shared__ float bs[FOUT];
    for (int i = threadIdx.x; i < FIN * FOUT; i += blockDim.x) Ws[i] = W[i];
    if (threadIdx.x < FOUT) bs[threadIdx.x] = bias[threadIdx.x];
    float a = 0.0f;
    if (PRELU) a = __ldg(aP);
    __syncthreads();

    int row = blockIdx.x * blockDim.x + threadIdx.x;
    if (row >= n) return;

    float r[FIN];
    const float4* zr = reinterpret_cast<const float4*>(z + (size_t)row * FIN);
#pragma unroll
    for (int k4 = 0; k4 < FIN / 4; k4++) {
        float4 v = __ldg(zr + k4);
        r[4 * k4 + 0] = v.x; r[4 * k4 + 1] = v.y;
        r[4 * k4 + 2] = v.z; r[4 * k4 + 3] = v.w;
    }
    float* orow = out + (size_t)row * FOUT;
#pragma unroll 2
    for (int c = 0; c < FOUT; c += 4) {
        float4 acc = {bs[c + 0], bs[c + 1], bs[c + 2], bs[c + 3]};
#pragma unroll
        for (int k = 0; k < FIN; k++) {
            float4 w = *reinterpret_cast<const float4*>(&Ws[k * FOUT + c]);
            acc.x += r[k] * w.x; acc.y += r[k] * w.y;
            acc.z += r[k] * w.z; acc.w += r[k] * w.w;
        }
        if (PRELU) {
            acc.x = acc.x >= 0.f ? acc.x : a * acc.x;
            acc.y = acc.y >= 0.f ? acc.y : a * acc.y;
            acc.z = acc.z >= 0.f ? acc.z : a * acc.z;
            acc.w = acc.w >= 0.f ? acc.w : a * acc.w;
        }
        *reinterpret_cast<float4*>(orow + c) = acc;
    }
}

// ---------------- pool z4 (64-wide mean per graph) + composed head ----------
__device__ __forceinline__ int lower_bound_i(const int* b, int n, int v) {
    int lo = 0, hi = n;
    while (lo < hi) {
        int m = (lo + hi) >> 1;
        if (__ldg(&b[m]) < v) lo = m + 1; else hi = m;
    }
    return lo;
}

__global__ void k_pool(const float* __restrict__ z, const int* __restrict__ batch,
                       const float* __restrict__ Wc, const float* __restrict__ bc,
                       float* __restrict__ out, int n) {
    const int F = 64;
    int g = blockIdx.x;
    int start = lower_bound_i(batch, n, g);
    int end   = lower_bound_i(batch, n, g + 1);

    int c   = threadIdx.x & (F - 1);
    int sub = threadIdx.x >> 6;          // 4 row-subsets
    float acc = 0.f;
    for (int r = start + sub; r < end; r += 4)
        acc += __ldg(&z[(size_t)r * F + c]);

    __shared__ float sm[256];
    __shared__ float pooled[F];
    sm[threadIdx.x] = acc;
    __syncthreads();
    if (threadIdx.x < F) {
        int cnt = end - start;
        float denom = (float)(cnt > 1 ? cnt : 1);
        pooled[threadIdx.x] = (sm[threadIdx.x] + sm[threadIdx.x + 64] +
                               sm[threadIdx.x + 128] + sm[threadIdx.x + 192]) / denom;
    }
    __syncthreads();
    if (threadIdx.x < 4) {
        float s = __ldg(&bc[threadIdx.x]);
#pragma unroll 8
        for (int f = 0; f < F; f++)
            s += pooled[f] * __ldg(&Wc[f * 4 + threadIdx.x]);
        out[g * 4 + threadIdx.x] = s;
    }
}

// ---------------------------------------------------------------------------
extern "C" void kernel_launch(void* const* d_in, const int* in_sizes, int n_in,
                              void* d_out, int out_size) {
    const float* x    = (const float*)d_in[0];
    const int* esrc   = (const int*)d_in[1];
    const int* edst   = (const int*)d_in[2];
    const int* batch  = (const int*)d_in[3];
    const float* W1   = (const float*)d_in[4];
    const float* b1   = (const float*)d_in[5];
    const float* W2   = (const float*)d_in[6];
    const float* b2   = (const float*)d_in[7];
    const float* W3   = (const float*)d_in[8];
    const float* b3   = (const float*)d_in[9];
    const float* W4   = (const float*)d_in[10];
    const float* b4   = (const float*)d_in[11];
    const float* a1   = (const float*)d_in[12];
    const float* a2   = (const float*)d_in[13];
    const float* a3   = (const float*)d_in[14];
    const float* Wlin = (const float*)d_in[15];
    const float* blin = (const float*)d_in[16];
    float* out = (float*)d_out;

    int n = in_sizes[0] / 8;   // x is [N, 8]
    int e = in_sizes[1];
    int G = out_size / 4;

    float *dinv, *cnorm, *z, *ha, *hb, *Wc, *bc;
    int *deg, *fill, *rowptr, *bsums, *col;
    cudaGetSymbolAddress((void**)&dinv,   g_dinv);
    cudaGetSymbolAddress((void**)&deg,    g_deg);
    cudaGetSymbolAddress((void**)&fill,   g_fill);
    cudaGetSymbolAddress((void**)&rowptr, g_rowptr);
    cudaGetSymbolAddress((void**)&bsums,  g_bsums);
    cudaGetSymbolAddress((void**)&col,    g_col);
    cudaGetSymbolAddress((void**)&cnorm,  g_cnorm);
    cudaGetSymbolAddress((void**)&z,      g_z);
    cudaGetSymbolAddress((void**)&ha,     g_ha);
    cudaGetSymbolAddress((void**)&hb,     g_hb);
    cudaGetSymbolAddress((void**)&Wc,     g_Wc);
    cudaGetSymbolAddress((void**)&bc,     g_bc);

    const int T = 256;
    int nscan = cdiv(n, SCAN_BLK);

    // degree, dinv, CSR build, head precompose
    k_zero <<<cdiv(n, T), T>>>(deg, fill, n);
    k_count<<<cdiv(e, T), T>>>(edst, deg, e);
    k_dinv <<<cdiv(n, T), T>>>(deg, dinv, n);
    k_scan1<<<nscan, SCAN_BLK>>>(deg, rowptr, bsums, n);
    k_scan2<<<1, 256>>>(bsums, nscan);
    k_scan3<<<cdiv(n, T), T>>>(rowptr, bsums, n, e);
    k_fillcsr<<<cdiv(e, T), T>>>(esrc, edst, dinv, rowptr, fill, col, cnorm, e);
    k_head<<<1, 256>>>(W4, b4, Wlin, blin, Wc, bc);

    // Layer 1: agg x (8) -> z ; gemm 8->16 +prelu -> ha
    k_agg<8> <<<cdiv((long)n * 2, T), T>>>(rowptr, col, cnorm, x, dinv, z, n);
    k_gemm<8, 16, true><<<cdiv(n, T), T>>>(z, W1, b1, a1, ha, n);

    // Layer 2: agg ha (16) -> z ; gemm 16->32 +prelu -> hb
    k_agg<16><<<cdiv((long)n * 4, T), T>>>(rowptr, col, cnorm, ha, dinv, z, n);
    k_gemm<16, 32, true><<<cdiv(n, T), T>>>(z, W2, b2, a2, hb, n);

    // Layer 3: agg hb (32) -> z ; gemm 32->64 +prelu -> ha
    k_agg<32><<<cdiv((long)n * 8, T), T>>>(rowptr, col, cnorm, hb, dinv, z, n);
    k_gemm<32, 64, true><<<cdiv(n, T), T>>>(z, W3, b3, a3, ha, n);

    // Layer 4 (linear): agg ha (64) -> z ; pool z + composed head
    k_agg<64><<<cdiv((long)n * 16, T), T>>>(rowptr, col, cnorm, ha, dinv, z, n);
    k_pool<<<G, 256>>>(z, batch, Wc, bc, out, n);
}